// round 5
// baseline (speedup 1.0000x reference)
#include <cuda_runtime.h>
#include <cstdint>

// FlowNet correlation: out[b, dy*21+dx, y, x] =
//   (1/256) * sum_c in1[b,c,y,x] * in2[b,c,y+2dy-20,x+2dx-20]
// B=8, C=256, H=96, W=128, zero padding outside.
#define B_SZ 8
#define C_SZ 256
#define H_SZ 96
#define W_SZ 128
#define G_SZ 21

#define CHUNK 4            // channels per smem tile
#define NCHUNK 64          // 256 / 4
#define NWARP 7            // warp <-> dy within triple
#define NT 224

// smem parity layouts (floats):
// A per channel (stride 160): even x -> idx x/2 (0..63); odd x -> 80 + (x-1)/2 (80..143)
// B per (dy,ch) slot (stride 224): even p -> p/2+10 (0..73, halos 0..9/74..83 zero)
//                                   odd  p -> 122+(p-1)/2 (112..185, halos 112..121/186..195 zero)
#define A_STRIDE 160
#define B_STRIDE 224
#define A_FLOATS (CHUNK * A_STRIDE)           // 640
#define B_FLOATS (NWARP * CHUNK * B_STRIDE)   // 6272
#define CH_STRIDE_F4 (CHUNK * H_SZ * (W_SZ / 4))   // 12288 (4-channel advance, float4 units)

__global__ __launch_bounds__(NT, 2)
void corr_kernel(const float* __restrict__ in1,
                 const float* __restrict__ in2,
                 float* __restrict__ out)
{
    __shared__ float sm[A_FLOATS + B_FLOATS];
    float* As = sm;
    float* Bs = sm + A_FLOATS;

    const int dyt = blockIdx.x;   // 0..2
    const int y   = blockIdx.y;   // 0..95
    const int b   = blockIdx.z;   // 0..7

    const int tid  = threadIdx.x;
    const int wid  = tid >> 5;    // 0..6
    const int lane = tid & 31;
    const int pi   = lane & 1;
    const int g    = lane >> 1;

    // ---- staging roles (warp-uniform rows; lane sweeps x4 -> coalesced) ----
    // B: k=0..3, row = wid + 7k in [0,28): row = w*CHUNK + cc
    int  gB[4];   bool okB[4];   int sB[4];
#pragma unroll
    for (int k = 0; k < 4; ++k) {
        int row = wid + NWARP * k;
        int wk = row >> 2, cck = row & 3;
        int yy = y + 2 * (dyt * NWARP + wk) - 20;
        okB[k] = ((unsigned)yy < (unsigned)H_SZ);
        int yyc = okB[k] ? yy : 0;
        gB[k] = ((b * C_SZ + cck) * H_SZ + yyc) * (W_SZ / 4) + lane;
        sB[k] = row * B_STRIDE;
    }
    const bool okA = tid < 128;
    const int  ccA = (tid >> 5) & 3;
    const int  gA  = ((b * C_SZ + ccA) * H_SZ + y) * (W_SZ / 4) + lane;

    const float4* in1f4 = (const float4*)in1;
    const float4* in2f4 = (const float4*)in2;

    // ---- consumer base pointers ----
    const float* ap = As + pi * 80 + 4 * g;
    const float* bp = Bs + wid * (CHUNK * B_STRIDE) + pi * 112 + 4 * g;

    float acc[4][21];
#pragma unroll
    for (int r = 0; r < 4; ++r)
#pragma unroll
        for (int d = 0; d < 21; ++d) acc[r][d] = 0.0f;

    // ---- zero B area once (x/y halos + out-of-range dy rows stay zero) ----
    {
        float4* b4 = (float4*)Bs;     // Bs is 16B aligned (A_FLOATS*4 = 2560)
#pragma unroll
        for (int k = 0; k < B_FLOATS / 4 / NT; ++k)   // 1568/224 = 7
            b4[tid + k * NT] = make_float4(0.f, 0.f, 0.f, 0.f);
    }

    // ---- register-staged pipeline ----
    float4 vB[4], vA;
#pragma unroll
    for (int k = 0; k < 4; ++k)
        if (okB[k]) vB[k] = in2f4[gB[k]];
    if (okA) vA = in1f4[gA];

#pragma unroll 1
    for (int ch = 0; ch < NCHUNK; ++ch) {
        __syncthreads();              // prev compute (or zero-fill) done
        // STS staged registers (parity split), conflict-free STS.64
#pragma unroll
        for (int k = 0; k < 4; ++k) {
            if (okB[k]) {
                float* bb = Bs + sB[k];
                ((float2*)(bb + 10))[lane]  = make_float2(vB[k].x, vB[k].z);
                ((float2*)(bb + 122))[lane] = make_float2(vB[k].y, vB[k].w);
            }
        }
        if (okA) {
            float* ab = As + ccA * A_STRIDE;
            ((float2*)ab)[lane]        = make_float2(vA.x, vA.z);
            ((float2*)(ab + 80))[lane] = make_float2(vA.y, vA.w);
        }
        __syncthreads();              // tile visible

        // issue next chunk's loads now; latency hides under compute below
        if (ch + 1 < NCHUNK) {
            const int o = (ch + 1) * CH_STRIDE_F4;
#pragma unroll
            for (int k = 0; k < 4; ++k)
                if (okB[k]) vB[k] = in2f4[gB[k] + o];
            if (okA) vA = in1f4[gA + o];
        }

        // ---- compute: 4 channels x 84 FMAs ----
#pragma unroll
        for (int cc = 0; cc < CHUNK; ++cc) {
            float4 av = *(const float4*)(ap + cc * A_STRIDE);
            const float* bq = bp + cc * B_STRIDE;

            float wv[16];
#pragma unroll
            for (int j = 0; j < 4; ++j) {
                float4 t = *(const float4*)(bq + 4 * j);
                wv[4*j] = t.x; wv[4*j+1] = t.y; wv[4*j+2] = t.z; wv[4*j+3] = t.w;
            }
#pragma unroll
            for (int d = 0; d <= 11; ++d) {            // needs idx d+3 <= 14
                acc[0][d] = fmaf(av.x, wv[d + 0], acc[0][d]);
                acc[1][d] = fmaf(av.y, wv[d + 1], acc[1][d]);
                acc[2][d] = fmaf(av.z, wv[d + 2], acc[2][d]);
                acc[3][d] = fmaf(av.w, wv[d + 3], acc[3][d]);
            }
            float wv2[12];                              // idx 12..23
#pragma unroll
            for (int j = 0; j < 3; ++j) {
                float4 t = *(const float4*)(bq + 12 + 4 * j);
                wv2[4*j] = t.x; wv2[4*j+1] = t.y; wv2[4*j+2] = t.z; wv2[4*j+3] = t.w;
            }
#pragma unroll
            for (int d = 12; d <= 20; ++d) {
                acc[0][d] = fmaf(av.x, wv2[d - 12], acc[0][d]);
                acc[1][d] = fmaf(av.y, wv2[d - 11], acc[1][d]);
                acc[2][d] = fmaf(av.z, wv2[d - 10], acc[2][d]);
                acc[3][d] = fmaf(av.w, wv2[d -  9], acc[3][d]);
            }
        }
    }
    __syncthreads();                  // all compute done before reusing smem

    // ---- epilogue: per-warp smem staging -> coalesced float4 stores ----
    float* stage = Bs + wid * 128;    // 7*128 = 896 <= 6272
    const float inv = 1.0f / 256.0f;
    const int xb = 8 * g + pi;
    float4* outf4 = (float4*)out;
    const int dy_idx = dyt * NWARP + wid;
    const int dbase = b * (G_SZ * G_SZ) + dy_idx * G_SZ;

#pragma unroll 1
    for (int d = 0; d < 21; ++d) {
        __syncwarp();
        stage[xb + 0] = acc[0][d] * inv;
        stage[xb + 2] = acc[1][d] * inv;
        stage[xb + 4] = acc[2][d] * inv;
        stage[xb + 6] = acc[3][d] * inv;
        __syncwarp();
        outf4[((dbase + d) * H_SZ + y) * (W_SZ / 4) + lane] =
            ((const float4*)stage)[lane];
    }
}

extern "C" void kernel_launch(void* const* d_in, const int* in_sizes, int n_in,
                              void* d_out, int out_size)
{
    const float* in1 = (const float*)d_in[0];
    const float* in2 = (const float*)d_in[1];
    float* out = (float*)d_out;

    dim3 grid(3, H_SZ, B_SZ);   // 2304 blocks
    corr_kernel<<<grid, NT>>>(in1, in2, out);
}

// round 6
// speedup vs baseline: 2.4366x; 2.4366x over previous
#include <cuda_runtime.h>
#include <cstdint>

// FlowNet correlation: out[b, dy*21+dx, y, x] =
//   (1/256) * sum_c in1[b,c,y,x] * in2[b,c,y+2dy-20,x+2dx-20]
// B=8, C=256, H=96, W=128, zero padding outside.
#define B_SZ 8
#define C_SZ 256
#define H_SZ 96
#define W_SZ 128
#define G_SZ 21

#define CHUNK 2            // channels per smem tile (small => few staging regs)
#define NCHUNK 128         // 256 / 2
#define NWARP 7
#define NT 224

// smem parity layouts (floats):
// A per channel (stride 160): even x -> x/2 (0..63); odd x -> 80+(x-1)/2 (80..143)
// B per (dy,ch) row (stride 224): even p -> p/2+10 (0..73; halos zero)
//                                  odd  p -> 122+(p-1)/2 (112..185; halos zero)
#define A_STRIDE 160
#define B_STRIDE 224
#define A_FLOATS (CHUNK * A_STRIDE)            // 320
#define B_FLOATS (NWARP * CHUNK * B_STRIDE)    // 3136
#define CH_F4 (CHUNK * H_SZ * (W_SZ / 4))      // 6144 float4 per chunk advance

#define FMAROW(d, m0, m1, m2, m3)          \
    acc0[d] = fmaf(av.x, m0, acc0[d]);     \
    acc1[d] = fmaf(av.y, m1, acc1[d]);     \
    acc2[d] = fmaf(av.z, m2, acc2[d]);     \
    acc3[d] = fmaf(av.w, m3, acc3[d]);

#define GROUP4(d0, P, Q)                   \
    FMAROW(d0 + 0, P.y, P.z, P.w, Q.x)     \
    FMAROW(d0 + 1, P.z, P.w, Q.x, Q.y)     \
    FMAROW(d0 + 2, P.w, Q.x, Q.y, Q.z)     \
    FMAROW(d0 + 3, Q.x, Q.y, Q.z, Q.w)

__global__ __launch_bounds__(NT, 2)
void corr_kernel(const float* __restrict__ in1,
                 const float* __restrict__ in2,
                 float* __restrict__ out)
{
    __shared__ float sm[A_FLOATS + B_FLOATS];
    float* As = sm;
    float* Bs = sm + A_FLOATS;

    const int dyt = blockIdx.x;   // 0..2
    const int y   = blockIdx.y;   // 0..95
    const int b   = blockIdx.z;   // 0..7

    const int tid  = threadIdx.x;
    const int wid  = tid >> 5;
    const int lane = tid & 31;
    const int pi   = lane & 1;
    const int g    = lane >> 1;

    // ---- staging roles: B = 14 rows x 32 f4 -> 2 f4/thread; A: tid<64, 1 f4 ----
    int gB[2]; bool okB[2]; int sB[2];
#pragma unroll
    for (int k = 0; k < 2; ++k) {
        int row = wid + NWARP * k;            // 0..13 = w*2 + cc
        int wk = row >> 1, cck = row & 1;
        int yy = y + 2 * (dyt * NWARP + wk) - 20;
        okB[k] = ((unsigned)yy < (unsigned)H_SZ);
        int yyc = okB[k] ? yy : 0;
        gB[k] = ((b * C_SZ + cck) * H_SZ + yyc) * (W_SZ / 4) + lane;
        sB[k] = row * B_STRIDE;
    }
    const bool okA = tid < 64;
    const int  ccA = tid >> 5;                 // 0..1
    int gA = ((b * C_SZ + ccA) * H_SZ + y) * (W_SZ / 4) + lane;

    const float4* in1f4 = (const float4*)in1;
    const float4* in2f4 = (const float4*)in2;

    const float* ap = As + pi * 80 + 4 * g;
    const float* bp = Bs + wid * (CHUNK * B_STRIDE) + pi * 112 + 4 * g;

    float acc0[21], acc1[21], acc2[21], acc3[21];
#pragma unroll
    for (int d = 0; d < 21; ++d) { acc0[d] = 0.f; acc1[d] = 0.f; acc2[d] = 0.f; acc3[d] = 0.f; }

    // ---- zero B area once (halos / out-of-range dy rows stay zero) ----
    {
        float4* b4 = (float4*)Bs;               // 16B aligned (A_FLOATS*4 = 1280)
#pragma unroll 1
        for (int i = tid; i < B_FLOATS / 4; i += NT)
            b4[i] = make_float4(0.f, 0.f, 0.f, 0.f);
    }

    // ---- prefetch chunk 0 ----
    float4 vB0, vB1, vA;
    if (okB[0]) vB0 = in2f4[gB[0]];
    if (okB[1]) vB1 = in2f4[gB[1]];
    if (okA)    vA  = in1f4[gA];

#pragma unroll 1
    for (int ch = 0; ch < NCHUNK; ++ch) {
        __syncthreads();                        // prev compute (or zero-fill) done
        if (okB[0]) {
            float* bb = Bs + sB[0];
            ((float2*)(bb + 10))[lane]  = make_float2(vB0.x, vB0.z);
            ((float2*)(bb + 122))[lane] = make_float2(vB0.y, vB0.w);
        }
        if (okB[1]) {
            float* bb = Bs + sB[1];
            ((float2*)(bb + 10))[lane]  = make_float2(vB1.x, vB1.z);
            ((float2*)(bb + 122))[lane] = make_float2(vB1.y, vB1.w);
        }
        if (okA) {
            float* ab = As + ccA * A_STRIDE;
            ((float2*)ab)[lane]        = make_float2(vA.x, vA.z);
            ((float2*)(ab + 80))[lane] = make_float2(vA.y, vA.w);
        }
        __syncthreads();                        // tile visible

        // issue next chunk's loads; latency hides under compute below
        if (ch + 1 < NCHUNK) {
            gB[0] += CH_F4; gB[1] += CH_F4; gA += CH_F4;
            if (okB[0]) vB0 = in2f4[gB[0]];
            if (okB[1]) vB1 = in2f4[gB[1]];
            if (okA)    vA  = in1f4[gA];
        }

        // ---- compute: 2 channels x 84 FMAs, rotating 6-float4 window ----
#pragma unroll
        for (int cc = 0; cc < CHUNK; ++cc) {
            float4 av = *(const float4*)(ap + cc * A_STRIDE);
            const float4* bq = (const float4*)(bp + cc * B_STRIDE);

            float4 w0 = bq[0], w1 = bq[1];
            FMAROW(0, w0.x, w0.y, w0.z, w0.w)
            float4 w2 = bq[2];
            GROUP4(1, w0, w1)
            float4 w3 = bq[3];
            GROUP4(5, w1, w2)
            float4 w4 = bq[4];
            GROUP4(9, w2, w3)
            float4 w5 = bq[5];
            GROUP4(13, w3, w4)
            GROUP4(17, w4, w5)
        }
    }
    __syncthreads();                            // compute done before smem reuse

    // ---- epilogue: per-warp smem staging -> coalesced float4 stores ----
    float* stage = Bs + wid * 128;              // 7*128 = 896 <= 3136
    const float inv = 1.0f / 256.0f;
    const int xb = 8 * g + pi;
    float4* outf4 = (float4*)out;
    const int dy_idx = dyt * NWARP + wid;
    const int dbase = b * (G_SZ * G_SZ) + dy_idx * G_SZ;

#pragma unroll 1
    for (int d = 0; d < 21; ++d) {
        __syncwarp();
        stage[xb + 0] = acc0[d] * inv;
        stage[xb + 2] = acc1[d] * inv;
        stage[xb + 4] = acc2[d] * inv;
        stage[xb + 6] = acc3[d] * inv;
        __syncwarp();
        outf4[((dbase + d) * H_SZ + y) * (W_SZ / 4) + lane] =
            ((const float4*)stage)[lane];
    }
}

extern "C" void kernel_launch(void* const* d_in, const int* in_sizes, int n_in,
                              void* d_out, int out_size)
{
    const float* in1 = (const float*)d_in[0];
    const float* in2 = (const float*)d_in[1];
    float* out = (float*)d_out;

    dim3 grid(3, H_SZ, B_SZ);   // 2304 blocks
    corr_kernel<<<grid, NT>>>(in1, in2, out);
}